// round 6
// baseline (speedup 1.0000x reference)
#include <cuda_runtime.h>

#define T_STEPS 2000
#define NB      1024
#define NMUL    16
#define NTH     128   // 4 warps -> SMSPs 0..3
#define NBLK    128   // 128*128 = 16384 threads = NB*NMUL
#define CH      16    // steps per chunk (= conv ring size = unroll)
#define NCHUNK  (T_STEPS / CH)   // 125, exact

__device__ __forceinline__ float fast_lg2(float a) {
    float r;
    asm("lg2.approx.f32 %0, %1;" : "=f"(r) : "f"(a));
    return r;
}
__device__ __forceinline__ float fast_ex2(float a) {
    float r;
    asm("ex2.approx.f32 %0, %1;" : "=f"(r) : "f"(a));
    return r;
}

__global__ void __launch_bounds__(NTH, 1)
hbv_kernel(const float* __restrict__ x,      // (T, B, 3)
           const float* __restrict__ ps,     // (B, 288)
           float* __restrict__ out)          // (T, B)
{
    // per-warp transpose buffer for the m-reduction (pad 17 -> conflict-free)
    __shared__ float red[4][2][16][17];

    const int m    = threadIdx.x & (NMUL - 1);
    const int w_id = threadIdx.x >> 5;
    const int lane = threadIdx.x & 31;
    const int cell = lane >> 4;
    const int tt   = lane & 15;

    const int gwarp = blockIdx.x * 4 + w_id;
    const int b     = gwarp * 2 + cell;        // this thread's grid cell
    const int b0    = gwarp * 2;               // warp's first cell

    const float* pb = ps + b * 288 + m;

    // --- physical parameters (parRT, parAC unused by the model) ---
    const float BETA   = 1.0f   + pb[0*16]  * 5.0f;
    const float FC     = 50.0f  + pb[1*16]  * 950.0f;
    const float K0     = 0.05f  + pb[2*16]  * 0.85f;
    const float K1     = 0.01f  + pb[3*16]  * 0.49f;
    const float K2     = 0.001f + pb[4*16]  * 0.199f;
    const float LP     = 0.2f   + pb[5*16]  * 0.8f;
    const float PERC   =          pb[6*16]  * 10.0f;
    const float UZL    =          pb[7*16]  * 100.0f;
    const float TT     = -2.5f  + pb[8*16]  * 5.0f;
    const float CFMAX  = 0.5f   + pb[9*16]  * 9.5f;
    const float CFR    =          pb[10*16] * 0.1f;
    const float CWH    =          pb[11*16] * 0.2f;
    const float BETAET = 0.3f   + pb[12*16] * 4.7f;
    const float Cpar   =          pb[13*16];

    const float invFC    = 1.0f / FC;
    const float bLP      = BETAET * fast_lg2(1.0f / LP);  // BETAET*lg2(1/LP)
    const float epsF     = 1e-5f * invFC;
    const float CFRCFMAX = CFR * CFMAX;
    const float CinvFC   = Cpar * invFC;                  // for s = SLZ*C/FC

    // --- routing weights (gammaln prefactor cancels under normalization) ---
    const float aa     = fmaxf(pb[256] * 2.9f, 0.0f) + 0.1f;
    const float theta  = fmaxf(pb[272] * 6.5f, 0.0f) + 0.5f;
    const float itheta = 1.0f / theta;

    float w[CH];
    float wsum = 0.0f;
#pragma unroll
    for (int k = 0; k < 15; ++k) {
        const float tk = (float)k + 0.5f;
        w[k] = expf((aa - 1.0f) * logf(tk) - tk * itheta);
        wsum += w[k];
    }
    const float iws = 1.0f / wsum;
#pragma unroll
    for (int k = 0; k < 15; ++k) w[k] *= iws;
    w[15] = 0.0f;                         // dummy tap so ring period == unroll

    // --- state (y = SM/FC normalized) ---
    float SP  = 1e-5f, MW = 1e-5f, SUZ = 1e-5f, SLZ = 1e-5f;
    float y   = epsF;

    float q[CH];
#pragma unroll
    for (int k = 0; k < CH; ++k) q[k] = 0.0f;

    const float* xr = x + (size_t)b * 3;
    float Pm = __ldg(xr + 0), Tc = __ldg(xr + 1), PE = __ldg(xr + 2);

#pragma unroll 1
    for (int c = 0; c < NCHUNK; ++c) {
#pragma unroll
        for (int j = 0; j < CH; ++j) {
            const int t = c * CH + j;
            // next step's forcing; ptxas hoists these across the unrolled chunk
            const int tn = (t + 1 < T_STEPS) ? (t + 1) : (T_STEPS - 1);
            const float* xp = xr + (size_t)tn * (NB * 3);
            const float Pn = __ldg(xp + 0);
            const float Tn = __ldg(xp + 1);
            const float En = __ldg(xp + 2);

            // --- snow routine (feeds inr ~24cyc, hidden under pow#1) ---
            const float rain = (Tc >= TT) ? Pm : 0.0f;
            const float snow = Pm - rain;
            const float m0 = fmaxf(CFMAX * (Tc - TT), 0.0f);       // off-chain
            const float r0 = fmaxf(CFRCFMAX * (TT - Tc), 0.0f);    // off-chain
            SP += snow;
            const float melt = fminf(m0, SP);
            MW += melt;  SP -= melt;
            const float refreeze = fminf(r0, MW);
            SP += refreeze;  MW -= refreeze;
            const float tosoil = fmaxf(fmaf(-CWH, SP, MW), 0.0f);
            MW -= tosoil;

            // --- soil routine (y = SM/FC), chain-minimized ---
            const float inr  = rain + tosoil;
            const float inrF = inr * invFC;                 // off y-chain
            const float yp   = y + inrF;                    // parallel with lg2
            const float s    = SLZ * CinvFC;                // off y-chain
            const float oms  = 1.0f - s;                    // off y-chain
            // sw = min(y^BETA,1) = ex2(min(BETA*lg2 y, 0))
            const float sw   = fast_ex2(fminf(BETA * fast_lg2(y), 0.0f));
            const float recharge = inr * sw;                // off y-chain
            const float y1 = fmaf(-inrF, sw, yp);           // y + inrF*(1-sw)
            const float excess = fmaxf(y1 - 1.0f, 0.0f) * FC;  // off y-chain
            const float y2 = fminf(y1, 1.0f);
            // capillary fused: y3 = y2 + s*(1-y2) = fma(y2, 1-s, s)
            const float y3 = fmaf(y2, oms, s);
            // SLZ update off the y-chain: cap = SLZ*max(C*(1-y1),0)
            const float cap = SLZ * fmaxf(fmaf(-Cpar, y1, Cpar), 0.0f);
            SLZ -= cap;
            // ef = min(y3/LP,1)^BETAET = ex2(min(BETAET*lg2(y3)+bLP, 0))
            const float ef  = fast_ex2(fminf(fmaf(fast_lg2(y3), BETAET, bLP), 0.0f));
            const float PEF = PE * invFC;                   // off y-chain
            y = fmaxf(fmaf(-PEF, ef, y3), epsF);            // fused ET + floor

            // --- response routine (parallel side-chain) ---
            SUZ += recharge + excess;
            const float PERCv = fminf(SUZ, PERC);
            SUZ -= PERCv;
            const float Q0 = K0 * fmaxf(SUZ - UZL, 0.0f);
            SUZ -= Q0;
            const float Q1 = K1 * SUZ;
            SUZ -= Q1;
            SLZ += PERCv;
            const float Q2 = K2 * SLZ;
            SLZ -= Q2;
            const float Qs = Q0 + Q1 + Q2;

            // --- routing conv: ring of 16 (renamed via unroll), 4 accumulators ---
            q[j] = Qs;
            float a0 = 0.f, a1 = 0.f, a2 = 0.f, a3 = 0.f;
#pragma unroll
            for (int k = 0; k < CH; k += 4) {
                a0 = fmaf(w[k + 0], q[(j - k - 0) & 15], a0);
                a1 = fmaf(w[k + 1], q[(j - k - 1) & 15], a1);
                a2 = fmaf(w[k + 2], q[(j - k - 2) & 15], a2);
                a3 = fmaf(w[k + 3], q[(j - k - 3) & 15], a3);
            }
            red[w_id][cell][m][j] = (a0 + a1) + (a2 + a3);  // STS: issue-only

            Pm = Pn; Tc = Tn; PE = En;
        }

        // --- per-16-step transpose reduce over m (no per-step shuffles) ---
        __syncwarp();
        {
            float s0 = 0.f, s1 = 0.f;
#pragma unroll
            for (int mi = 0; mi < 16; mi += 2) {
                s0 += red[w_id][cell][mi + 0][tt];
                s1 += red[w_id][cell][mi + 1][tt];
            }
            out[(c * CH + tt) * NB + (b0 + cell)] = (s0 + s1) * 0.0625f;
        }
        __syncwarp();
    }
}

extern "C" void kernel_launch(void* const* d_in, const int* in_sizes, int n_in,
                              void* d_out, int out_size)
{
    const float* x  = (const float*)d_in[0];
    const float* ps = (const float*)d_in[1];
    if (n_in >= 2 && in_sizes[0] == NB * 288) {  // swapped order
        x  = (const float*)d_in[1];
        ps = (const float*)d_in[0];
    }
    float* out = (float*)d_out;
    hbv_kernel<<<NBLK, NTH>>>(x, ps, out);
}

// round 7
// speedup vs baseline: 1.0712x; 1.0712x over previous
#include <cuda_runtime.h>

#define T_STEPS 2000
#define NB      1024
#define NMUL    16
#define NTH     128   // 4 warps -> SMSPs 0..3
#define NBLK    128   // 128*128 = 16384 threads = NB*NMUL
#define CH      16    // steps per chunk (= conv ring size = unroll)
#define NCHUNK  (T_STEPS / CH)   // 125, exact
#define PF      4     // forcing prefetch depth (~500 cyc ahead > L2 latency)

__device__ __forceinline__ float fast_lg2(float a) {
    float r;
    asm("lg2.approx.f32 %0, %1;" : "=f"(r) : "f"(a));
    return r;
}
__device__ __forceinline__ float fast_ex2(float a) {
    float r;
    asm("ex2.approx.f32 %0, %1;" : "=f"(r) : "f"(a));
    return r;
}

__global__ void __launch_bounds__(NTH, 1)
hbv_kernel(const float* __restrict__ x,      // (T, B, 3)
           const float* __restrict__ ps,     // (B, 288)
           float* __restrict__ out)          // (T, B)
{
    // per-warp transpose buffer for the m-reduction (pad 17 -> conflict-free)
    __shared__ float red[4][2][16][17];

    const int m    = threadIdx.x & (NMUL - 1);
    const int w_id = threadIdx.x >> 5;
    const int lane = threadIdx.x & 31;
    const int cell = lane >> 4;
    const int tt   = lane & 15;

    const int gwarp = blockIdx.x * 4 + w_id;
    const int b     = gwarp * 2 + cell;        // this thread's grid cell
    const int b0    = gwarp * 2;               // warp's first cell

    const float* pb = ps + b * 288 + m;

    // --- physical parameters (parRT, parAC unused by the model) ---
    const float BETA   = 1.0f   + pb[0*16]  * 5.0f;
    const float FC     = 50.0f  + pb[1*16]  * 950.0f;
    const float K0     = 0.05f  + pb[2*16]  * 0.85f;
    const float K1     = 0.01f  + pb[3*16]  * 0.49f;
    const float K2     = 0.001f + pb[4*16]  * 0.199f;
    const float LP     = 0.2f   + pb[5*16]  * 0.8f;
    const float PERC   =          pb[6*16]  * 10.0f;
    const float UZL    =          pb[7*16]  * 100.0f;
    const float TT     = -2.5f  + pb[8*16]  * 5.0f;
    const float CFMAX  = 0.5f   + pb[9*16]  * 9.5f;
    const float CFR    =          pb[10*16] * 0.1f;
    const float CWH    =          pb[11*16] * 0.2f;
    const float BETAET = 0.3f   + pb[12*16] * 4.7f;
    const float Cpar   =          pb[13*16];

    const float invFC    = 1.0f / FC;
    const float bLP      = BETAET * fast_lg2(1.0f / LP);  // BETAET*lg2(1/LP)
    const float epsF     = 1e-5f * invFC;
    const float CFRCFMAX = CFR * CFMAX;
    const float CinvFC   = Cpar * invFC;                  // for s = SLZ*C/FC

    // --- routing weights (gammaln prefactor cancels under normalization) ---
    const float aa     = fmaxf(pb[256] * 2.9f, 0.0f) + 0.1f;
    const float theta  = fmaxf(pb[272] * 6.5f, 0.0f) + 0.5f;
    const float itheta = 1.0f / theta;

    float w[CH];
    float wsum = 0.0f;
#pragma unroll
    for (int k = 0; k < 15; ++k) {
        const float tk = (float)k + 0.5f;
        w[k] = expf((aa - 1.0f) * logf(tk) - tk * itheta);
        wsum += w[k];
    }
    const float iws = 1.0f / wsum;
#pragma unroll
    for (int k = 0; k < 15; ++k) w[k] *= iws;
    w[15] = 0.0f;                         // dummy tap so ring period == unroll

    // --- state (y = SM/FC normalized; invariant y in (0,1]) ---
    float SP  = 1e-5f, MW = 1e-5f, SUZ = 1e-5f, SLZ = 1e-5f;
    float y   = epsF;

    float q[CH];
#pragma unroll
    for (int k = 0; k < CH; ++k) q[k] = 0.0f;

    // --- forcing prefetch ring: depth PF=4, register resident ---
    const float* xr = x + (size_t)b * 3;
    float Pf[PF], Tf[PF], Ef[PF];
#pragma unroll
    for (int k = 0; k < PF; ++k) {
        const float* xp = xr + (size_t)k * (NB * 3);
        Pf[k] = __ldg(xp + 0);
        Tf[k] = __ldg(xp + 1);
        Ef[k] = __ldg(xp + 2);
    }

#pragma unroll 1
    for (int c = 0; c < NCHUNK; ++c) {
#pragma unroll
        for (int j = 0; j < CH; ++j) {
            const int t = c * CH + j;
            const int s4 = j & (PF - 1);           // == t & 3 (CH multiple of PF)

            const float Pm = Pf[s4], Tc = Tf[s4], PE = Ef[s4];

            // refill slot with forcing for step t+PF (clamped; used 4 steps later)
            {
                const int tn = (t + PF < T_STEPS) ? (t + PF) : (T_STEPS - 1);
                const float* xp = xr + (size_t)tn * (NB * 3);
                Pf[s4] = __ldg(xp + 0);
                Tf[s4] = __ldg(xp + 1);
                Ef[s4] = __ldg(xp + 2);
            }

            // --- snow routine (feeds inr; runs in parallel with lg2 chain) ---
            const float rain = (Tc >= TT) ? Pm : 0.0f;
            const float snow = Pm - rain;
            const float m0 = fmaxf(CFMAX * (Tc - TT), 0.0f);       // off-chain
            const float r0 = fmaxf(CFRCFMAX * (TT - Tc), 0.0f);    // off-chain
            SP += snow;
            const float melt = fminf(m0, SP);
            MW += melt;  SP -= melt;
            const float refreeze = fminf(r0, MW);
            SP += refreeze;  MW -= refreeze;
            const float tosoil = fmaxf(fmaf(-CWH, SP, MW), 0.0f);
            MW -= tosoil;

            // --- soil routine (y = SM/FC), chain-minimized ---
            const float inr  = rain + tosoil;
            const float inrF = inr * invFC;                 // off y-chain
            const float yp   = y + inrF;                    // parallel with lg2
            const float s    = SLZ * CinvFC;                // off y-chain
            const float oms  = 1.0f - s;                    // off y-chain
            // y in (0,1], BETA>=1 -> BETA*lg2(y)<=0 -> sw in (0,1]: no clamps
            const float sw   = fast_ex2(BETA * fast_lg2(y));
            const float recharge = inr * sw;                // off y-chain
            const float y1 = fmaf(-inrF, sw, yp);           // y + inrF*(1-sw)
            const float excess = fmaxf(y1 - 1.0f, 0.0f) * FC;  // off y-chain
            const float y2 = fminf(y1, 1.0f);
            // capillary fused: y3 = y2 + s*(1-y2) = fma(y2, 1-s, s)
            const float y3 = fmaf(y2, oms, s);
            // SLZ update off the y-chain: cap = SLZ*max(C*(1-y1),0)
            const float cap = SLZ * fmaxf(fmaf(-Cpar, y1, Cpar), 0.0f);
            SLZ -= cap;
            // ef = min(y3/LP,1)^BETAET = ex2(min(BETAET*lg2(y3)+bLP, 0))
            const float ef  = fast_ex2(fminf(fmaf(fast_lg2(y3), BETAET, bLP), 0.0f));
            const float PEF = PE * invFC;                   // off y-chain
            y = fmaxf(fmaf(-PEF, ef, y3), epsF);            // fused ET + floor

            // --- response routine (parallel side-chain) ---
            SUZ += recharge + excess;
            const float PERCv = fminf(SUZ, PERC);
            SUZ -= PERCv;
            const float Q0 = K0 * fmaxf(SUZ - UZL, 0.0f);
            SUZ -= Q0;
            const float Q1 = K1 * SUZ;
            SUZ -= Q1;
            SLZ += PERCv;
            const float Q2 = K2 * SLZ;
            SLZ -= Q2;
            const float Qs = Q0 + Q1 + Q2;

            // --- routing conv: ring of 16 (renamed via unroll), 4 accumulators ---
            q[j] = Qs;
            float a0 = 0.f, a1 = 0.f, a2 = 0.f, a3 = 0.f;
#pragma unroll
            for (int k = 0; k < CH; k += 4) {
                a0 = fmaf(w[k + 0], q[(j - k - 0) & 15], a0);
                a1 = fmaf(w[k + 1], q[(j - k - 1) & 15], a1);
                a2 = fmaf(w[k + 2], q[(j - k - 2) & 15], a2);
                a3 = fmaf(w[k + 3], q[(j - k - 3) & 15], a3);
            }
            red[w_id][cell][m][j] = (a0 + a1) + (a2 + a3);  // STS: issue-only
        }

        // --- per-16-step transpose reduce over m (no per-step shuffles) ---
        __syncwarp();
        {
            float s0 = 0.f, s1 = 0.f;
#pragma unroll
            for (int mi = 0; mi < 16; mi += 2) {
                s0 += red[w_id][cell][mi + 0][tt];
                s1 += red[w_id][cell][mi + 1][tt];
            }
            out[(c * CH + tt) * NB + (b0 + cell)] = (s0 + s1) * 0.0625f;
        }
        __syncwarp();
    }
}

extern "C" void kernel_launch(void* const* d_in, const int* in_sizes, int n_in,
                              void* d_out, int out_size)
{
    const float* x  = (const float*)d_in[0];
    const float* ps = (const float*)d_in[1];
    if (n_in >= 2 && in_sizes[0] == NB * 288) {  // swapped order
        x  = (const float*)d_in[1];
        ps = (const float*)d_in[0];
    }
    float* out = (float*)d_out;
    hbv_kernel<<<NBLK, NTH>>>(x, ps, out);
}